// round 4
// baseline (speedup 1.0000x reference)
#include <cuda_runtime.h>
#include <math.h>

#define Bsz   32
#define Tlen  2048
#define Hdim  512
#define Gdim  2048
#define HB    (Hdim*Bsz)      // 16384
#define NBS   32              // blocks per GEMM stage
#define NBA0  4               // embedding gather blocks
#define RPB   64              // gate rows per block
#define UPB   16              // hidden units per recurrent block
#define LAG   64              // run-ahead throttle (keeps traffic in L2)
#define WPAD  65              // padded W smem row stride (bank-conflict-free)
#define GPAD  34              // padded gate-exchange stride (8B-aligned, 2-way max)

#define SM_W    (Hdim*WPAD)   // 33280 floats
#define SM_IN   HB            // 16384
#define SM_GATE (RPB*GPAD)    // 2176
#define SM_C    (UPB*Bsz)     // 512
#define SMEM_FLOATS (SM_W+SM_IN+SM_GATE+SM_C)
#define SMEM_BYTES  (SMEM_FLOATS*4)   // 209408 < 227KB

// ---------------- global scratch (allocation-free __device__ globals) ------
static __device__ __align__(16) float g_embT[(size_t)Tlen*HB];
static __device__ __align__(16) float g_ix1[(size_t)Tlen*Gdim*Bsz];
static __device__ __align__(16) float g_ix2[(size_t)Tlen*Gdim*Bsz];
static __device__ __align__(16) float g_h1[(size_t)(Tlen+1)*HB];
static __device__ __align__(16) float g_h2[(size_t)(Tlen+1)*HB];
static __device__ int g_f_embT[Tlen];
static __device__ int g_f_ix1[Tlen];
static __device__ int g_f_ix2[Tlen];
static __device__ int g_f_h1[Tlen+1];
static __device__ int g_f_h2[Tlen+1];

// ---------------- helpers --------------------------------------------------
union U64F2 { unsigned long long u; float2 f; };

__device__ __forceinline__ float sigf(float x) { return 1.0f / (1.0f + expf(-x)); }

__device__ __forceinline__ void spin(volatile int* p, int v) {
    while (*p < v) __nanosleep(40);
}

// 64KB input tile global(L2) -> smem, coalesced float4, L1-bypassing
__device__ __forceinline__ void copy_in(float* insm, const float* __restrict__ src, int tid) {
    const float4* s = reinterpret_cast<const float4*>(src);
    float4* d = reinterpret_cast<float4*>(insm);
#pragma unroll
    for (int i = 0; i < 16; ++i) d[tid + i*256] = __ldcg(s + tid + i*256);
}

// Stage W slice [64 rows x 512 k] into smem, k-major with pad (conflict-free ld/st)
__device__ __forceinline__ void load_W(float* Wsm, const float* __restrict__ Wg,
                                       int rowbase, bool strided, int j, int tid) {
    for (int idx = tid; idx < RPB*Hdim; idx += 256) {
        int rl = idx >> 9, k = idx & 511;
        int grow = strided ? ((rl >> 4)*Hdim + j*UPB + (rl & 15)) : (rowbase + rl);
        Wsm[k*WPAD + rl] = Wg[(size_t)grow*Hdim + k];
    }
}

// out[r][q*8..q*8+7] = sum_k Wsm[k][r] * insm[k][b]; packed f32x2 FMA
__device__ __forceinline__ void gemm64(const float* __restrict__ Wsm,
                                       const float* __restrict__ insm,
                                       int r, int q, unsigned long long acc[4]) {
    acc[0] = acc[1] = acc[2] = acc[3] = 0ull;
    const float* ip = insm + q*8;
#pragma unroll 16
    for (int k = 0; k < Hdim; ++k) {
        float w = Wsm[k*WPAD + r];
        unsigned long long w2;
        asm("mov.b64 %0, {%1, %1};" : "=l"(w2) : "f"(w));
        const ulonglong2* v = reinterpret_cast<const ulonglong2*>(ip + k*Bsz);
        ulonglong2 v0 = v[0];
        ulonglong2 v1 = *reinterpret_cast<const ulonglong2*>(ip + k*Bsz + 4);
        asm("fma.rn.f32x2 %0, %1, %2, %0;" : "+l"(acc[0]) : "l"(w2), "l"(v0.x));
        asm("fma.rn.f32x2 %0, %1, %2, %0;" : "+l"(acc[1]) : "l"(w2), "l"(v0.y));
        asm("fma.rn.f32x2 %0, %1, %2, %0;" : "+l"(acc[2]) : "l"(w2), "l"(v1.x));
        asm("fma.rn.f32x2 %0, %1, %2, %0;" : "+l"(acc[3]) : "l"(w2), "l"(v1.y));
    }
}

// ---------------- pipeline stages -----------------------------------------
// Feed-forward projection: out[t] = W @ in[t+slot_off] + bias  (runs ahead, throttled)
__device__ void stage_ff(int j, int tid, float* Wsm, float* insm,
                         const float* Wg, const float* biasA, const float* biasB,
                         const float* inbase, int slot_off, int* f_in, int in_thresh,
                         float* outbase, int* f_out, int* f_throttle) {
    load_W(Wsm, Wg, j*RPB, false, j, tid);
    int r = (tid & 31) | (((tid >> 5) & 1) << 5);
    int q = tid >> 6;
    float bias = biasA[j*RPB + r] + biasB[j*RPB + r];
    for (int t = 0; t < Tlen; ++t) {
        if (tid == 0) {
            spin(&f_in[t + slot_off], in_thresh);
            if (t >= LAG) spin(&f_throttle[t - LAG], NBS);
            __threadfence();
        }
        __syncthreads();
        copy_in(insm, inbase + (size_t)(t + slot_off)*HB, tid);
        __syncthreads();
        unsigned long long acc[4];
        gemm64(Wsm, insm, r, q, acc);
        float2* op = reinterpret_cast<float2*>(outbase + ((size_t)t*Gdim + j*RPB + r)*Bsz + q*8);
#pragma unroll
        for (int m = 0; m < 4; ++m) { U64F2 u; u.u = acc[m]; u.f.x += bias; u.f.y += bias; op[m] = u.f; }
        __threadfence();
        __syncthreads();
        if (tid == 0) atomicAdd(&f_out[t], 1);
    }
}

// Recurrence: gates = W_hh @ h[t] + ix[t]; pointwise LSTM cell; h[t+1] out.
__device__ void stage_rec(int j, int tid, float* Wsm, float* insm, float* gsm, float* csm,
                          const float* Wg, const float* ixbase, int* f_ix,
                          float* hbase, int* f_h) {
    load_W(Wsm, Wg, 0, true, j, tid);
    csm[tid] = 0.f; csm[tid + 256] = 0.f;
    int r = (tid & 31) | (((tid >> 5) & 1) << 5);
    int q = tid >> 6;
    int grow = (r >> 4)*Hdim + j*UPB + (r & 15);
    for (int t = 0; t < Tlen; ++t) {
        if (tid == 0) { spin(&f_ix[t], NBS); spin(&f_h[t], NBS); __threadfence(); }
        __syncthreads();
        copy_in(insm, hbase + (size_t)t*HB, tid);
        __syncthreads();
        unsigned long long acc[4];
        gemm64(Wsm, insm, r, q, acc);
        const float2* ixp = reinterpret_cast<const float2*>(ixbase + ((size_t)t*Gdim + grow)*Bsz + q*8);
        float2* gp = reinterpret_cast<float2*>(gsm + r*GPAD + q*8);
#pragma unroll
        for (int m = 0; m < 4; ++m) {
            U64F2 u; u.u = acc[m];
            float2 iv = __ldcg(ixp + m);
            u.f.x += iv.x; u.f.y += iv.y;
            gp[m] = u.f;
        }
        __syncthreads();
#pragma unroll
        for (int e = 0; e < 2; ++e) {
            int idx = tid + e*256;
            int uu = idx >> 5, b = idx & 31;
            float gi = gsm[uu*GPAD + b];
            float gf = gsm[(16 + uu)*GPAD + b];
            float gg = gsm[(32 + uu)*GPAD + b];
            float go = gsm[(48 + uu)*GPAD + b];
            float c = sigf(gf)*csm[idx] + sigf(gi)*tanhf(gg);
            float h = sigf(go)*tanhf(c);
            csm[idx] = c;
            hbase[(size_t)(t + 1)*HB + (j*UPB + uu)*Bsz + b] = h;
        }
        __threadfence();
        __syncthreads();
        if (tid == 0) atomicAdd(&f_h[t + 1], 1);
    }
}

// ---------------- kernels --------------------------------------------------
__global__ void reset_kernel() {
    int i = blockIdx.x*256 + threadIdx.x;   // 16384 threads
    if (i < Tlen) { g_f_embT[i] = 0; g_f_ix1[i] = 0; g_f_ix2[i] = 0; }
    if (i <= Tlen) { g_f_h1[i] = (i == 0) ? NBS : 0; g_f_h2[i] = (i == 0) ? NBS : 0; }
    if (i < HB) { g_h1[i] = 0.f; g_h2[i] = 0.f; }
}

__global__ void __launch_bounds__(256, 1)
lstm_persist(const int* __restrict__ x, const int* __restrict__ labels,
             const float* __restrict__ emb,
             const float* __restrict__ Wih, const float* __restrict__ Whh,
             const float* __restrict__ bih, const float* __restrict__ bhh,
             const float* __restrict__ fcw, const float* __restrict__ fcb,
             float* __restrict__ out, int out_size) {
    extern __shared__ float sm[];
    int bid = blockIdx.x, tid = threadIdx.x;
    float* Wsm  = sm;
    float* insm = sm + SM_W;
    float* gsm  = insm + SM_IN;
    float* csm  = gsm + SM_GATE;

    if (bid < NBA0) {
        // ---- embedding gather + transpose: embT[t][h][b] = emb[x[b][t]][h]
        float* tsm = sm;                      // [b][h] staging, stride 513
        __shared__ int rows[Bsz];
        for (int t = bid; t < Tlen; t += NBA0) {
            if (tid == 0 && t >= LAG) spin(&g_f_ix1[t - LAG], NBS);
            __syncthreads();
            if (tid < Bsz) rows[tid] = x[tid*Tlen + t];
            __syncthreads();
#pragma unroll
            for (int it = 0; it < 16; ++it) {
                int b = it*2 + (tid >> 7);
                int h4 = tid & 127;
                float4 v = *reinterpret_cast<const float4*>(emb + (size_t)rows[b]*Hdim + h4*4);
                tsm[b*513 + h4*4 + 0] = v.x; tsm[b*513 + h4*4 + 1] = v.y;
                tsm[b*513 + h4*4 + 2] = v.z; tsm[b*513 + h4*4 + 3] = v.w;
            }
            __syncthreads();
            int b = tid & 31, hb = tid >> 5;
#pragma unroll 8
            for (int hh = 0; hh < 64; ++hh) {
                int h = hb*64 + hh;
                g_embT[(size_t)t*HB + h*Bsz + b] = tsm[b*513 + h];
            }
            __threadfence();
            __syncthreads();
            if (tid == 0) atomicAdd(&g_f_embT[t], 1);
        }
        return;
    }

    int role = (bid - NBA0) >> 5;   // 0=ix1, 1=rec1, 2=ix2, 3=rec2
    int j = (bid - NBA0) & 31;

    if (role == 0) {
        stage_ff(j, tid, Wsm, insm, Wih, bih, bhh,
                 g_embT, 0, g_f_embT, NBA0 == 4 ? 1 : 1, g_ix1, g_f_ix1, g_f_h1);
    } else if (role == 1) {
        stage_rec(j, tid, Wsm, insm, gsm, csm, Whh, g_ix1, g_f_ix1, g_h1, g_f_h1);
    } else if (role == 2) {
        stage_ff(j, tid, Wsm, insm, Wih + (size_t)Gdim*Hdim, bih + Gdim, bhh + Gdim,
                 g_h1, 1, g_f_h1, NBS, g_ix2, g_f_ix2, g_f_h2);
    } else {
        stage_rec(j, tid, Wsm, insm, gsm, csm, Whh + (size_t)Gdim*Hdim,
                  g_ix2, g_f_ix2, g_h2, g_f_h2);
        if (j == 0) {
            // ---- classifier + log-softmax + NLL on final h2
            if (tid == 0) { spin(&g_f_h2[Tlen], NBS); __threadfence(); }
            __syncthreads();
            float* ls = gsm;   // reuse smem for logits[32][4]
            if (tid < 128) {
                int n = tid & 3, b = tid >> 2;
                float a = fcb[n];
                const float* w = fcw + n*Hdim;
                const float* h2 = g_h2 + (size_t)Tlen*HB;
                for (int h = 0; h < Hdim; ++h) a += w[h]*h2[h*Bsz + b];
                ls[b*4 + n] = a;
            }
            __syncthreads();
            if (tid == 0) {
                float loss = 0.f;
                for (int b = 0; b < Bsz; ++b) {
                    float l0 = ls[b*4], l1 = ls[b*4+1], l2 = ls[b*4+2], l3 = ls[b*4+3];
                    float m = fmaxf(fmaxf(l0, l1), fmaxf(l2, l3));
                    float s = expf(l0-m) + expf(l1-m) + expf(l2-m) + expf(l3-m);
                    float lse = m + logf(s);
                    loss -= (ls[b*4 + labels[b]] - lse);
                }
                loss /= (float)Bsz;
                if (out_size >= 129) {
                    out[0] = loss;
                    for (int i = 0; i < 128; ++i) out[1 + i] = ls[i];
                    for (int i = 129; i < out_size; ++i) out[i] = 0.f;
                } else if (out_size == 128) {
                    for (int i = 0; i < 128; ++i) out[i] = ls[i];
                } else {
                    out[0] = loss;
                    for (int i = 1; i < out_size; ++i) out[i] = ls[i - 1];
                }
            }
        }
    }
}

// ---------------- launch ---------------------------------------------------
extern "C" void kernel_launch(void* const* d_in, const int* in_sizes, int n_in,
                              void* d_out, int out_size) {
    const int*   x      = (const int*)d_in[0];
    const int*   labels = (const int*)d_in[1];
    const float* emb    = (const float*)d_in[2];
    const float* Wih    = (const float*)d_in[3];
    const float* Whh    = (const float*)d_in[4];
    const float* bih    = (const float*)d_in[5];
    const float* bhh    = (const float*)d_in[6];
    const float* fcw    = (const float*)d_in[7];
    const float* fcb    = (const float*)d_in[8];
    (void)in_sizes; (void)n_in;

    cudaFuncSetAttribute(lstm_persist, cudaFuncAttributeMaxDynamicSharedMemorySize, SMEM_BYTES);
    reset_kernel<<<64, 256>>>();
    lstm_persist<<<NBA0 + 4*NBS, 256, SMEM_BYTES>>>(
        x, labels, emb, Wih, Whh, bih, bhh, fcw, fcb, (float*)d_out, out_size);
}

// round 7
// speedup vs baseline: 1.2979x; 1.2979x over previous
#include <cuda_runtime.h>
#include <math.h>

#define Bsz   32
#define Tlen  2048
#define Hdim  512
#define Gdim  2048
#define HB    (Hdim*Bsz)      // 16384
#define NBS   32              // blocks per GEMM stage
#define NBA0  4               // embedding gather blocks
#define RPB   64              // gate rows per block
#define UPB   16              // hidden units per recurrent block
#define LAG   64              // run-ahead throttle (keeps traffic in L2)
#define THR   512
#define GPAD  34              // gate-exchange row stride (float2-aligned)
#define PPAD  33              // partial-buffer row stride (conflict-free scalar)
#define PSTR  (RPB*PPAD)      // 2112 floats per kh-partial plane

// smem layout (floats)
#define SM_W    (Hdim*RPB)            // 32768 (interleaved pairs)
#define SM_IN   HB                    // 16384
#define SM_PART (3*PSTR)              // 6336
#define SM_GATE (RPB*GPAD)            // 2176
#define SMEM_FLOATS (SM_W+SM_IN+SM_PART+SM_GATE)   // 57664
#define SMEM_BYTES  (SMEM_FLOATS*4)                // 230656 <= 232448

// ---------------- global scratch ------------------------------------------
static __device__ __align__(16) float g_embT[(size_t)Tlen*HB];
static __device__ __align__(16) float g_ix1[(size_t)Tlen*Gdim*Bsz];
static __device__ __align__(16) float g_ix2[(size_t)Tlen*Gdim*Bsz];
static __device__ __align__(16) float g_h1[(size_t)(Tlen+1)*HB];
static __device__ __align__(16) float g_h2[(size_t)(Tlen+1)*HB];
static __device__ int g_f_embT[Tlen];
static __device__ int g_f_ix1[Tlen];
static __device__ int g_f_ix2[Tlen];
static __device__ int g_f_h1[Tlen+1];
static __device__ int g_f_h2[Tlen+1];

// ---------------- helpers --------------------------------------------------
union U64F2 { unsigned long long u; float2 f; };

__device__ __forceinline__ float sigf(float x) { return 1.0f / (1.0f + expf(-x)); }

__device__ __forceinline__ void spin(volatile int* p, int v) {
    while (*p < v) __nanosleep(40);
}

// 64KB input tile global(L2) -> smem, coalesced float4
__device__ __forceinline__ void copy_in(float* insm, const float* __restrict__ src, int tid) {
    const float4* s = reinterpret_cast<const float4*>(src);
    float4* d = reinterpret_cast<float4*>(insm);
#pragma unroll
    for (int i = 0; i < 8; ++i) d[tid + i*THR] = __ldcg(s + tid + i*THR);
}

// Stage W slice [64 rows x 512 k] into smem, k-major, rows interleaved as
// pairs (r, r+32) so the inner loop fetches both rows with one LDS.64.
__device__ __forceinline__ void load_W(float* Wsm, const float* __restrict__ Wg,
                                       int rowbase, bool strided, int j, int tid) {
    for (int idx = tid; idx < RPB*Hdim; idx += THR) {
        int rl = idx >> 9, k = idx & 511;
        int grow = strided ? ((rl >> 4)*Hdim + j*UPB + (rl & 15)) : (rowbase + rl);
        Wsm[k*RPB + (rl & 31)*2 + (rl >> 5)] = Wg[(size_t)grow*Hdim + k];
    }
}

// Split-K GEMM: thread (lane,q,kh) accumulates rows {lane, lane+32} x batch
// q*8..q*8+7 over k in [kh*128, kh*128+128).
__device__ __forceinline__ void gemm2(const float* __restrict__ Wsm,
                                      const float* __restrict__ insm,
                                      int lane, int q, int kh,
                                      unsigned long long acc[8]) {
#pragma unroll
    for (int i = 0; i < 8; ++i) acc[i] = 0ull;
    const float* ip = insm + q*8;
    const float* wp = Wsm + kh*128*RPB + lane*2;
#pragma unroll 8
    for (int kk = 0; kk < 128; ++kk) {
        float2 w = *reinterpret_cast<const float2*>(wp + kk*RPB);
        unsigned long long wa, wb;
        asm("mov.b64 %0, {%1, %1};" : "=l"(wa) : "f"(w.x));
        asm("mov.b64 %0, {%1, %1};" : "=l"(wb) : "f"(w.y));
        const ulonglong2* v = reinterpret_cast<const ulonglong2*>(ip + (kh*128 + kk)*Bsz);
        ulonglong2 v0 = v[0];
        ulonglong2 v1 = *reinterpret_cast<const ulonglong2*>(ip + (kh*128 + kk)*Bsz + 4);
        asm("fma.rn.f32x2 %0, %1, %2, %0;" : "+l"(acc[0]) : "l"(wa), "l"(v0.x));
        asm("fma.rn.f32x2 %0, %1, %2, %0;" : "+l"(acc[1]) : "l"(wa), "l"(v0.y));
        asm("fma.rn.f32x2 %0, %1, %2, %0;" : "+l"(acc[2]) : "l"(wa), "l"(v1.x));
        asm("fma.rn.f32x2 %0, %1, %2, %0;" : "+l"(acc[3]) : "l"(wa), "l"(v1.y));
        asm("fma.rn.f32x2 %0, %1, %2, %0;" : "+l"(acc[4]) : "l"(wb), "l"(v0.x));
        asm("fma.rn.f32x2 %0, %1, %2, %0;" : "+l"(acc[5]) : "l"(wb), "l"(v0.y));
        asm("fma.rn.f32x2 %0, %1, %2, %0;" : "+l"(acc[6]) : "l"(wb), "l"(v1.x));
        asm("fma.rn.f32x2 %0, %1, %2, %0;" : "+l"(acc[7]) : "l"(wb), "l"(v1.y));
    }
}

__device__ __forceinline__ void write_partials(float* part, int kh, int lane, int q,
                                               const unsigned long long acc[8]) {
#pragma unroll
    for (int rr = 0; rr < 2; ++rr) {
        float* pp = part + (kh-1)*PSTR + (lane + rr*32)*PPAD + q*8;
#pragma unroll
        for (int m = 0; m < 4; ++m) {
            U64F2 u; u.u = acc[rr*4 + m];
            pp[2*m] = u.f.x; pp[2*m + 1] = u.f.y;
        }
    }
}

// ---------------- pipeline stages -----------------------------------------
__device__ void stage_ff(int j, int tid, float* Wsm, float* insm, float* part,
                         const float* Wg, const float* biasA, const float* biasB,
                         const float* inbase, int slot_off, int* f_in, int in_thresh,
                         float* outbase, int* f_out, int* f_throttle) {
    load_W(Wsm, Wg, j*RPB, false, j, tid);
    int lane = tid & 31, w = tid >> 5, q = w & 3, kh = w >> 2;
    float bias0 = biasA[j*RPB + lane]       + biasB[j*RPB + lane];
    float bias1 = biasA[j*RPB + lane + 32]  + biasB[j*RPB + lane + 32];
    for (int t = 0; t < Tlen; ++t) {
        if (tid == 0) {
            spin(&f_in[t + slot_off], in_thresh);
            if (t >= LAG) spin(&f_throttle[t - LAG], NBS);
            __threadfence();
        }
        __syncthreads();
        copy_in(insm, inbase + (size_t)(t + slot_off)*HB, tid);
        __syncthreads();
        unsigned long long acc[8];
        gemm2(Wsm, insm, lane, q, kh, acc);
        if (kh > 0) write_partials(part, kh, lane, q, acc);
        __syncthreads();
        if (kh == 0) {
#pragma unroll
            for (int rr = 0; rr < 2; ++rr) {
                int r = lane + rr*32;
                float bias = rr ? bias1 : bias0;
                const float* pp = part + r*PPAD + q*8;
                float2* op = reinterpret_cast<float2*>(
                    outbase + ((size_t)t*Gdim + j*RPB + r)*Bsz + q*8);
#pragma unroll
                for (int m = 0; m < 4; ++m) {
                    U64F2 u; u.u = acc[rr*4 + m];
                    float2 g;
                    g.x = u.f.x + pp[2*m]   + pp[PSTR + 2*m]   + pp[2*PSTR + 2*m]   + bias;
                    g.y = u.f.y + pp[2*m+1] + pp[PSTR + 2*m+1] + pp[2*PSTR + 2*m+1] + bias;
                    op[m] = g;
                }
            }
        }
        __threadfence();
        __syncthreads();
        if (tid == 0) atomicAdd(&f_out[t], 1);
    }
}

__device__ void stage_rec(int j, int tid, float* Wsm, float* insm, float* part, float* gsm,
                          const float* Wg, const float* ixbase, int* f_ix,
                          float* hbase, int* f_h) {
    load_W(Wsm, Wg, 0, true, j, tid);
    int lane = tid & 31, w = tid >> 5, q = w & 3, kh = w >> 2;
    int cu = tid >> 5, cb = tid & 31;          // cell mapping: unit, batch
    float creg = 0.f;                          // cell state in register
    for (int t = 0; t < Tlen; ++t) {
        if (tid == 0) { spin(&f_ix[t], NBS); spin(&f_h[t], NBS); __threadfence(); }
        __syncthreads();
        copy_in(insm, hbase + (size_t)t*HB, tid);
        __syncthreads();
        unsigned long long acc[8];
        gemm2(Wsm, insm, lane, q, kh, acc);
        float2 ixr[8];
        if (kh == 0) {
#pragma unroll
            for (int rr = 0; rr < 2; ++rr) {
                int r = lane + rr*32;
                int G = (r >> 4)*Hdim + j*UPB + (r & 15);
                const float2* ip2 = reinterpret_cast<const float2*>(
                    ixbase + ((size_t)t*Gdim + G)*Bsz + q*8);
#pragma unroll
                for (int m = 0; m < 4; ++m) ixr[rr*4 + m] = __ldcg(ip2 + m);
            }
        } else {
            write_partials(part, kh, lane, q, acc);
        }
        __syncthreads();
        if (kh == 0) {
#pragma unroll
            for (int rr = 0; rr < 2; ++rr) {
                int r = lane + rr*32;
                const float* pp = part + r*PPAD + q*8;
                float2* gp = reinterpret_cast<float2*>(gsm + r*GPAD + q*8);
#pragma unroll
                for (int m = 0; m < 4; ++m) {
                    U64F2 u; u.u = acc[rr*4 + m];
                    float2 g;
                    g.x = u.f.x + pp[2*m]   + pp[PSTR + 2*m]   + pp[2*PSTR + 2*m]   + ixr[rr*4+m].x;
                    g.y = u.f.y + pp[2*m+1] + pp[PSTR + 2*m+1] + pp[2*PSTR + 2*m+1] + ixr[rr*4+m].y;
                    gp[m] = g;
                }
            }
        }
        __syncthreads();
        {   // LSTM cell: one (unit,batch) per thread
            float gi = gsm[cu*GPAD + cb];
            float gf = gsm[(UPB   + cu)*GPAD + cb];
            float gg = gsm[(2*UPB + cu)*GPAD + cb];
            float go = gsm[(3*UPB + cu)*GPAD + cb];
            creg = sigf(gf)*creg + sigf(gi)*tanhf(gg);
            float h = sigf(go)*tanhf(creg);
            hbase[(size_t)(t + 1)*HB + (j*UPB + cu)*Bsz + cb] = h;
        }
        __threadfence();
        __syncthreads();
        if (tid == 0) atomicAdd(&f_h[t + 1], 1);
    }
}

// ---------------- kernels --------------------------------------------------
__global__ void reset_kernel() {
    int i = blockIdx.x*256 + threadIdx.x;   // 16384 threads
    if (i < Tlen) { g_f_embT[i] = 0; g_f_ix1[i] = 0; g_f_ix2[i] = 0; }
    if (i <= Tlen) { g_f_h1[i] = (i == 0) ? NBS : 0; g_f_h2[i] = (i == 0) ? NBS : 0; }
    if (i < HB) { g_h1[i] = 0.f; g_h2[i] = 0.f; }
}

__global__ void __launch_bounds__(THR, 1)
lstm_persist(const int* __restrict__ x, const int* __restrict__ labels,
             const float* __restrict__ emb,
             const float* __restrict__ Wih, const float* __restrict__ Whh,
             const float* __restrict__ bih, const float* __restrict__ bhh,
             const float* __restrict__ fcw, const float* __restrict__ fcb,
             float* __restrict__ out, int out_size) {
    extern __shared__ float sm[];
    int bid = blockIdx.x, tid = threadIdx.x;
    float* Wsm  = sm;
    float* insm = sm + SM_W;
    float* part = insm + SM_IN;
    float* gsm  = part + SM_PART;

    if (bid < NBA0) {
        // ---- embedding gather + transpose: embT[t][h][b] = emb[x[b][t]][h]
        float* tsm = sm;                       // [b][h] staging, stride 513
        int* rows = reinterpret_cast<int*>(sm + 17000);
        for (int t = bid; t < Tlen; t += NBA0) {
            if (tid == 0 && t >= LAG) spin(&g_f_ix1[t - LAG], NBS);
            __syncthreads();
            if (tid < Bsz) rows[tid] = x[tid*Tlen + t];
            __syncthreads();
#pragma unroll
            for (int i = 0; i < 8; ++i) {
                int idx = tid + i*THR;         // 0..4095
                int b = idx >> 7, h4 = idx & 127;
                float4 v = *reinterpret_cast<const float4*>(emb + (size_t)rows[b]*Hdim + h4*4);
                tsm[b*513 + h4*4 + 0] = v.x; tsm[b*513 + h4*4 + 1] = v.y;
                tsm[b*513 + h4*4 + 2] = v.z; tsm[b*513 + h4*4 + 3] = v.w;
            }
            __syncthreads();
            int b = tid & 31, hb = tid >> 5;
#pragma unroll 8
            for (int hh = 0; hh < 32; ++hh) {
                int h = hb*32 + hh;
                g_embT[(size_t)t*HB + h*Bsz + b] = tsm[b*513 + h];
            }
            __threadfence();
            __syncthreads();
            if (tid == 0) atomicAdd(&g_f_embT[t], 1);
        }
        return;
    }

    int role = (bid - NBA0) >> 5;   // 0=ix1, 1=rec1, 2=ix2, 3=rec2
    int j = (bid - NBA0) & 31;

    if (role == 0) {
        stage_ff(j, tid, Wsm, insm, part, Wih, bih, bhh,
                 g_embT, 0, g_f_embT, 1, g_ix1, g_f_ix1, g_f_h1);
    } else if (role == 1) {
        stage_rec(j, tid, Wsm, insm, part, gsm, Whh, g_ix1, g_f_ix1, g_h1, g_f_h1);
    } else if (role == 2) {
        stage_ff(j, tid, Wsm, insm, part, Wih + (size_t)Gdim*Hdim, bih + Gdim, bhh + Gdim,
                 g_h1, 1, g_f_h1, NBS, g_ix2, g_f_ix2, g_f_h2);
    } else {
        stage_rec(j, tid, Wsm, insm, part, gsm, Whh + (size_t)Gdim*Hdim,
                  g_ix2, g_f_ix2, g_h2, g_f_h2);
        if (j == 0) {
            // ---- classifier + log-softmax + NLL on final h2
            if (tid == 0) { spin(&g_f_h2[Tlen], NBS); __threadfence(); }
            __syncthreads();
            float* ls = gsm;   // reuse smem for logits[32][4]
            if (tid < 128) {
                int n = tid & 3, b = tid >> 2;
                float a = fcb[n];
                const float* wv = fcw + n*Hdim;
                const float* h2 = g_h2 + (size_t)Tlen*HB;
                for (int h = 0; h < Hdim; ++h) a += wv[h]*h2[h*Bsz + b];
                ls[b*4 + n] = a;
            }
            __syncthreads();
            if (tid == 0) {
                float loss = 0.f;
                for (int b = 0; b < Bsz; ++b) {
                    float l0 = ls[b*4], l1 = ls[b*4+1], l2 = ls[b*4+2], l3 = ls[b*4+3];
                    float m = fmaxf(fmaxf(l0, l1), fmaxf(l2, l3));
                    float s = expf(l0-m) + expf(l1-m) + expf(l2-m) + expf(l3-m);
                    float lse = m + logf(s);
                    loss -= (ls[b*4 + labels[b]] - lse);
                }
                loss /= (float)Bsz;
                if (out_size >= 129) {
                    out[0] = loss;
                    for (int i = 0; i < 128; ++i) out[1 + i] = ls[i];
                    for (int i = 129; i < out_size; ++i) out[i] = 0.f;
                } else if (out_size == 128) {
                    for (int i = 0; i < 128; ++i) out[i] = ls[i];
                } else {
                    out[0] = loss;
                    for (int i = 1; i < out_size; ++i) out[i] = ls[i - 1];
                }
            }
        }
    }
}

// ---------------- launch ---------------------------------------------------
extern "C" void kernel_launch(void* const* d_in, const int* in_sizes, int n_in,
                              void* d_out, int out_size) {
    const int*   x      = (const int*)d_in[0];
    const int*   labels = (const int*)d_in[1];
    const float* emb    = (const float*)d_in[2];
    const float* Wih    = (const float*)d_in[3];
    const float* Whh    = (const float*)d_in[4];
    const float* bih    = (const float*)d_in[5];
    const float* bhh    = (const float*)d_in[6];
    const float* fcw    = (const float*)d_in[7];
    const float* fcb    = (const float*)d_in[8];
    (void)in_sizes; (void)n_in;

    cudaFuncSetAttribute(lstm_persist, cudaFuncAttributeMaxDynamicSharedMemorySize, SMEM_BYTES);
    reset_kernel<<<64, 256>>>();
    lstm_persist<<<NBA0 + 4*NBS, THR, SMEM_BYTES>>>(
        x, labels, emb, Wih, Whh, bih, bhh, fcw, fcb, (float*)d_out, out_size);
}